// round 1
// baseline (speedup 1.0000x reference)
#include <cuda_runtime.h>
#include <math.h>

// Problem dims
#define BB 2
#define CC 128
#define HH 48
#define WW 48
#define GG 4
#define DHD 32
#define NPIX 2304   // 48*48
#define HD 12
#define JD 144      // 12*12
#define BG 8        // B*G

// Scratch (allocation-free: __device__ globals)
__device__ float g_q[BG * DHD * NPIX];   // q per (bg, d, i)
__device__ float g_vn0[BG * JD];
__device__ float g_vn1[BG * JD];
__device__ float g_k[BG * JD * DHD];     // (bg, j, d)
__device__ float g_v[BG * JD * DHD];
__device__ float g_o[BB * CC * NPIX];    // attention head outputs, (b, c=g*32+d, i)

// ---------------------------------------------------------------------------
// K1: grouped 1x1 conv -> q.  grid (9, 8), block 256. thread = one pixel i.
// ---------------------------------------------------------------------------
__global__ void k_qproj(const float* __restrict__ x, const float* __restrict__ wq) {
    int bg = blockIdx.y;
    int g  = bg & 3;
    int b  = bg >> 2;
    int i  = blockIdx.x * 256 + threadIdx.x;

    __shared__ float wqs[32 * 32];
    for (int t = threadIdx.x; t < 1024; t += 256) wqs[t] = wq[g * 1024 + t];
    __syncthreads();
    if (i >= NPIX) return;

    float acc[32];
#pragma unroll
    for (int o = 0; o < 32; o++) acc[o] = 0.f;

    const float* xp = x + (size_t)(b * CC + g * 32) * NPIX + i;
#pragma unroll 4
    for (int c = 0; c < 32; c++) {
        float xv = xp[c * NPIX];
#pragma unroll
        for (int o = 0; o < 32; o++) acc[o] = fmaf(xv, wqs[o * 32 + c], acc[o]);
    }
#pragma unroll
    for (int o = 0; o < 32; o++) g_q[(bg * 32 + o) * NPIX + i] = acc[o];
}

// ---------------------------------------------------------------------------
// K2: depthwise conv (k=6,s=4,p=1) -> GELU -> 1x1 -> tanh*4 -> grid ->
//     bilinear sample of x group -> k/v projection.  grid 8, block 144.
// ---------------------------------------------------------------------------
__global__ void k_offsets(const float* __restrict__ x,
                          const float* __restrict__ wdw, const float* __restrict__ bdw,
                          const float* __restrict__ wproj,
                          const float* __restrict__ wk, const float* __restrict__ wv) {
    int bg = blockIdx.x;
    int g  = bg & 3;
    int b  = bg >> 2;
    int j  = threadIdx.x;
    if (j >= JD) return;
    int ox = j % HD;
    int oy = j / HD;

    // depthwise conv + GELU + offset projection
    float p0 = 0.f, p1 = 0.f;
    for (int c = 0; c < 32; c++) {
        float s = 0.f;
        const float* qc = g_q + (size_t)(bg * 32 + c) * NPIX;
        const float* wc = wdw + c * 36;
#pragma unroll
        for (int ky = 0; ky < 6; ky++) {
            int iy = oy * 4 - 1 + ky;
            if (iy < 0 || iy >= HH) continue;
#pragma unroll
            for (int kx = 0; kx < 6; kx++) {
                int ix = ox * 4 - 1 + kx;
                if (ix < 0 || ix >= WW) continue;
                s = fmaf(qc[iy * WW + ix], wc[ky * 6 + kx], s);
            }
        }
        float t  = s + bdw[c];
        float ge = 0.5f * t * (1.f + erff(t * 0.70710678118654752f));  // exact GELU
        p0 = fmaf(ge, wproj[c],      p0);
        p1 = fmaf(ge, wproj[32 + c], p1);
    }
    float o0 = tanhf(p0) * 4.f;
    float o1 = tanhf(p1) * 4.f;

    float vg0 = (float)ox + o0;
    float vg1 = (float)oy + o1;
    float vn0 = 2.f * vg0 / 11.f - 1.f;
    float vn1 = 2.f * vg1 / 11.f - 1.f;
    g_vn0[bg * JD + j] = vn0;
    g_vn1[bg * JD + j] = vn1;

    // align_corners=False un-normalization
    float px = ((vn0 + 1.f) * (float)WW - 1.f) * 0.5f;
    float py = ((vn1 + 1.f) * (float)HH - 1.f) * 0.5f;

    // bilinear sample with zeros padding
    float x0 = floorf(px), y0 = floorf(py);
    float wx1 = px - x0, wy1 = py - y0;
    int ix0 = (int)x0, iy0 = (int)y0;
    float w00 = (1.f - wx1) * (1.f - wy1);
    float w10 = wx1 * (1.f - wy1);
    float w01 = (1.f - wx1) * wy1;
    float w11 = wx1 * wy1;
    bool vx0 = (ix0 >= 0) && (ix0 <= WW - 1);
    bool vx1 = (ix0 + 1 >= 0) && (ix0 + 1 <= WW - 1);
    bool vy0 = (iy0 >= 0) && (iy0 <= HH - 1);
    bool vy1 = (iy0 + 1 >= 0) && (iy0 + 1 <= HH - 1);
    int cx0 = min(max(ix0, 0), WW - 1), cx1 = min(max(ix0 + 1, 0), WW - 1);
    int cy0 = min(max(iy0, 0), HH - 1), cy1 = min(max(iy0 + 1, 0), HH - 1);

    float kv[32];
    const float* xb = x + (size_t)(b * CC + g * 32) * NPIX;
#pragma unroll 4
    for (int c = 0; c < 32; c++) {
        const float* xc = xb + c * NPIX;
        float a = 0.f;
        if (vx0 && vy0) a = fmaf(xc[cy0 * WW + cx0], w00, a);
        if (vx1 && vy0) a = fmaf(xc[cy0 * WW + cx1], w10, a);
        if (vx0 && vy1) a = fmaf(xc[cy1 * WW + cx0], w01, a);
        if (vx1 && vy1) a = fmaf(xc[cy1 * WW + cx1], w11, a);
        kv[c] = a;
    }

    const float* wkg = wk + g * 1024;
    const float* wvg = wv + g * 1024;
    for (int o = 0; o < 32; o++) {
        float ak = 0.f, av = 0.f;
#pragma unroll
        for (int c = 0; c < 32; c++) {
            ak = fmaf(kv[c], wkg[o * 32 + c], ak);
            av = fmaf(kv[c], wvg[o * 32 + c], av);
        }
        g_k[(bg * JD + j) * 32 + o] = ak;
        g_v[(bg * JD + j) * 32 + o] = av;
    }
}

// ---------------------------------------------------------------------------
// K3: fused attention: sim + CPB bias MLP + online softmax + attn@v.
//     grid (8, 36), block 64; one thread per query row i.
// ---------------------------------------------------------------------------
__global__ void __launch_bounds__(64)
k_attn(const float* __restrict__ cw0, const float* __restrict__ cb0,
       const float* __restrict__ cw1, const float* __restrict__ cb1,
       const float* __restrict__ cw2, const float* __restrict__ cb2) {
    int bg = blockIdx.x;
    int i  = blockIdx.y * 64 + threadIdx.x;
    int t  = threadIdx.x;

    __shared__ float ks[JD * 32];
    __shared__ float vs[JD * 32];
    __shared__ float w1s[32 * 32];
    __shared__ float vn0s[JD], vn1s[JD];
    __shared__ float w0s[64], b0s[32], b1s[32], w2s[32];
    __shared__ float b2s;

    for (int idx = t; idx < JD * 32; idx += 64) {
        ks[idx] = g_k[bg * JD * 32 + idx];
        vs[idx] = g_v[bg * JD * 32 + idx];
    }
    for (int idx = t; idx < 1024; idx += 64) w1s[idx] = cw1[idx];
    for (int idx = t; idx < JD; idx += 64) {
        vn0s[idx] = g_vn0[bg * JD + idx];
        vn1s[idx] = g_vn1[bg * JD + idx];
    }
    if (t < 64) w0s[t] = cw0[t];
    if (t < 32) { b0s[t] = cb0[t]; b1s[t] = cb1[t]; w2s[t] = cw2[t]; }
    if (t == 0) b2s = cb2[0];
    __syncthreads();

    const float scale = 0.17677669529663687f;  // 32^-0.5
    float qreg[32];
#pragma unroll
    for (int d = 0; d < 32; d++) qreg[d] = g_q[(bg * 32 + d) * NPIX + i] * scale;

    float qn0 = 2.f * (float)(i % 48) / 47.f - 1.f;   // x coordinate
    float qn1 = 2.f * (float)(i / 48) / 47.f - 1.f;   // y coordinate

    float m = -INFINITY, ssum = 0.f;
    float acc[32];
#pragma unroll
    for (int d = 0; d < 32; d++) acc[d] = 0.f;
    float b2v = b2s;

#pragma unroll 1
    for (int j = 0; j < JD; j++) {
        float dx = qn0 - vn0s[j];
        float dy = qn1 - vn1s[j];
        float fx = copysignf(log1pf(fabsf(dx)), dx);
        float fy = copysignf(log1pf(fabsf(dy)), dy);

        // layer 0: 2 -> 32
        float h1[32];
#pragma unroll
        for (int c = 0; c < 32; c++)
            h1[c] = fmaxf(fmaf(fy, w0s[32 + c], fmaf(fx, w0s[c], b0s[c])), 0.f);

        // layer 1: 32 -> 32 (independent accumulators, float4 LDS of W1 rows)
        float h2[32];
#pragma unroll
        for (int c = 0; c < 32; c++) h2[c] = b1s[c];
#pragma unroll
        for (int c1 = 0; c1 < 32; c1++) {
            float hv = h1[c1];
            const float4* wr = (const float4*)&w1s[c1 * 32];
#pragma unroll
            for (int q4 = 0; q4 < 8; q4++) {
                float4 w4 = wr[q4];
                h2[q4 * 4 + 0] = fmaf(hv, w4.x, h2[q4 * 4 + 0]);
                h2[q4 * 4 + 1] = fmaf(hv, w4.y, h2[q4 * 4 + 1]);
                h2[q4 * 4 + 2] = fmaf(hv, w4.z, h2[q4 * 4 + 2]);
                h2[q4 * 4 + 3] = fmaf(hv, w4.w, h2[q4 * 4 + 3]);
            }
        }
        // layer 2: 32 -> 1
        float bias = b2v;
#pragma unroll
        for (int c = 0; c < 32; c++) bias = fmaf(fmaxf(h2[c], 0.f), w2s[c], bias);

        // sim = q . k_j
        float sim = 0.f;
        const float4* kr = (const float4*)&ks[j * 32];
#pragma unroll
        for (int q4 = 0; q4 < 8; q4++) {
            float4 k4 = kr[q4];
            sim = fmaf(qreg[q4 * 4 + 0], k4.x, sim);
            sim = fmaf(qreg[q4 * 4 + 1], k4.y, sim);
            sim = fmaf(qreg[q4 * 4 + 2], k4.z, sim);
            sim = fmaf(qreg[q4 * 4 + 3], k4.w, sim);
        }
        float logit = sim + bias;

        // online softmax
        float nm   = fmaxf(m, logit);
        float corr = __expf(m - nm);
        float p    = __expf(logit - nm);
        ssum = fmaf(ssum, corr, p);
        const float4* vr = (const float4*)&vs[j * 32];
#pragma unroll
        for (int q4 = 0; q4 < 8; q4++) {
            float4 v4 = vr[q4];
            acc[q4 * 4 + 0] = fmaf(p, v4.x, acc[q4 * 4 + 0] * corr);
            acc[q4 * 4 + 1] = fmaf(p, v4.y, acc[q4 * 4 + 1] * corr);
            acc[q4 * 4 + 2] = fmaf(p, v4.z, acc[q4 * 4 + 2] * corr);
            acc[q4 * 4 + 3] = fmaf(p, v4.w, acc[q4 * 4 + 3] * corr);
        }
        m = nm;
    }

    float inv = 1.f / ssum;
#pragma unroll
    for (int d = 0; d < 32; d++) g_o[(bg * 32 + d) * NPIX + i] = acc[d] * inv;
}

// ---------------------------------------------------------------------------
// K4: output 1x1 projection + residual; writes both tuple outputs.
//     grid (36, 2), block 256 = 64 pixels x 4 channel chunks.
// ---------------------------------------------------------------------------
__global__ void k_outproj(const float* __restrict__ x, const float* __restrict__ wo,
                          const float* __restrict__ bo, const float* __restrict__ gamma,
                          float* __restrict__ out, int out_size) {
    int b  = blockIdx.y;
    int t  = threadIdx.x;
    int it = t & 63;
    int oc = t >> 6;        // 0..3 -> output channels [oc*32, oc*32+32)
    int i  = blockIdx.x * 64 + it;

    __shared__ float os[128 * 64];   // out columns for this pixel tile
    for (int idx = t; idx < 128 * 64; idx += 256) {
        int c = idx >> 6, ii = idx & 63;
        os[idx] = g_o[(size_t)(b * CC + c) * NPIX + blockIdx.x * 64 + ii];
    }
    __syncthreads();

    float acc[32];
#pragma unroll
    for (int o = 0; o < 32; o++) acc[o] = bo[oc * 32 + o];

    for (int c = 0; c < CC; c++) {
        float v = os[c * 64 + it];
#pragma unroll
        for (int o = 0; o < 32; o++)
            acc[o] = fmaf(v, __ldg(&wo[(oc * 32 + o) * CC + c]), acc[o]);
    }

    float gm = gamma[0];
    const int n1 = BB * CC * NPIX;
#pragma unroll
    for (int o = 0; o < 32; o++) {
        int ch  = oc * 32 + o;
        int idx = (b * CC + ch) * NPIX + i;
        float att = acc[o];
        if (idx < out_size) out[idx] = fmaf(gm, att, x[idx]);
        int idx2 = n1 + idx;
        if (idx2 < out_size) out[idx2] = att;
    }
}

// ---------------------------------------------------------------------------
extern "C" void kernel_launch(void* const* d_in, const int* in_sizes, int n_in,
                              void* d_out, int out_size) {
    const float* x     = (const float*)d_in[0];
    const float* gamma = (const float*)d_in[1];
    const float* wq    = (const float*)d_in[2];
    const float* wk    = (const float*)d_in[3];
    const float* wv    = (const float*)d_in[4];
    const float* wo    = (const float*)d_in[5];
    const float* bo    = (const float*)d_in[6];
    const float* wdw   = (const float*)d_in[7];
    const float* bdw   = (const float*)d_in[8];
    const float* wproj = (const float*)d_in[9];
    const float* cw0   = (const float*)d_in[10];
    const float* cb0   = (const float*)d_in[11];
    const float* cw1   = (const float*)d_in[12];
    const float* cb1   = (const float*)d_in[13];
    const float* cw2   = (const float*)d_in[14];
    const float* cb2   = (const float*)d_in[15];
    float* out = (float*)d_out;

    k_qproj<<<dim3(9, 8), 256>>>(x, wq);
    k_offsets<<<8, 144>>>(x, wdw, bdw, wproj, wk, wv);
    k_attn<<<dim3(8, 36), 64>>>(cw0, cb0, cw1, cb1, cw2, cb2);
    k_outproj<<<dim3(36, 2), 256>>>(x, wo, bo, gamma, out, out_size);
}

// round 3
// speedup vs baseline: 12.9927x; 12.9927x over previous
#include <cuda_runtime.h>
#include <math.h>

// Problem dims
#define BB 2
#define CC 128
#define HH 48
#define WW 48
#define GG 4
#define DHD 32
#define NPIX 2304   // 48*48
#define HD 12
#define JD 144      // 12*12
#define BG 8        // B*G
#define TI 32       // query tile per attention block
#define BSTR 145    // padded bias row stride

// Scratch (allocation-free: __device__ globals)
__device__ float g_q[BG * DHD * NPIX];   // q per (bg, d, i)
__device__ float g_vn0[BG * JD];
__device__ float g_vn1[BG * JD];
__device__ float g_k[BG * JD * DHD];     // (bg, j, d)
__device__ float g_v[BG * JD * DHD];
__device__ float g_o[BB * CC * NPIX];    // attention head outputs, (b, c=g*32+d, i)

// ---------------------------------------------------------------------------
// K1: grouped 1x1 conv -> q.  grid (9, 8), block 256. thread = one pixel i.
// ---------------------------------------------------------------------------
__global__ void k_qproj(const float* __restrict__ x, const float* __restrict__ wq) {
    int bg = blockIdx.y;
    int g  = bg & 3;
    int b  = bg >> 2;
    int i  = blockIdx.x * 256 + threadIdx.x;

    __shared__ float wqs[32 * 32];
    for (int t = threadIdx.x; t < 1024; t += 256) wqs[t] = wq[g * 1024 + t];
    __syncthreads();
    if (i >= NPIX) return;

    float acc[32];
#pragma unroll
    for (int o = 0; o < 32; o++) acc[o] = 0.f;

    const float* xp = x + (size_t)(b * CC + g * 32) * NPIX + i;
#pragma unroll 4
    for (int c = 0; c < 32; c++) {
        float xv = xp[c * NPIX];
#pragma unroll
        for (int o = 0; o < 32; o++) acc[o] = fmaf(xv, wqs[o * 32 + c], acc[o]);
    }
#pragma unroll
    for (int o = 0; o < 32; o++) g_q[(bg * 32 + o) * NPIX + i] = acc[o];
}

// ---------------------------------------------------------------------------
// K2: depthwise conv (k=6,s=4,p=1) -> GELU -> 1x1 -> tanh*4 -> grid ->
//     bilinear sample of x group -> k/v projection.  grid 8, block 144.
// ---------------------------------------------------------------------------
__global__ void k_offsets(const float* __restrict__ x,
                          const float* __restrict__ wdw, const float* __restrict__ bdw,
                          const float* __restrict__ wproj,
                          const float* __restrict__ wk, const float* __restrict__ wv) {
    int bg = blockIdx.x;
    int g  = bg & 3;
    int b  = bg >> 2;
    int j  = threadIdx.x;
    if (j >= JD) return;
    int ox = j % HD;
    int oy = j / HD;

    float p0 = 0.f, p1 = 0.f;
    for (int c = 0; c < 32; c++) {
        float s = 0.f;
        const float* qc = g_q + (size_t)(bg * 32 + c) * NPIX;
        const float* wc = wdw + c * 36;
#pragma unroll
        for (int ky = 0; ky < 6; ky++) {
            int iy = oy * 4 - 1 + ky;
            if (iy < 0 || iy >= HH) continue;
#pragma unroll
            for (int kx = 0; kx < 6; kx++) {
                int ix = ox * 4 - 1 + kx;
                if (ix < 0 || ix >= WW) continue;
                s = fmaf(qc[iy * WW + ix], wc[ky * 6 + kx], s);
            }
        }
        float t  = s + bdw[c];
        float ge = 0.5f * t * (1.f + erff(t * 0.70710678118654752f));
        p0 = fmaf(ge, wproj[c],      p0);
        p1 = fmaf(ge, wproj[32 + c], p1);
    }
    float o0 = tanhf(p0) * 4.f;
    float o1 = tanhf(p1) * 4.f;

    float vg0 = (float)ox + o0;
    float vg1 = (float)oy + o1;
    float vn0 = 2.f * vg0 / 11.f - 1.f;
    float vn1 = 2.f * vg1 / 11.f - 1.f;
    g_vn0[bg * JD + j] = vn0;
    g_vn1[bg * JD + j] = vn1;

    float px = ((vn0 + 1.f) * (float)WW - 1.f) * 0.5f;
    float py = ((vn1 + 1.f) * (float)HH - 1.f) * 0.5f;

    float x0 = floorf(px), y0 = floorf(py);
    float wx1 = px - x0, wy1 = py - y0;
    int ix0 = (int)x0, iy0 = (int)y0;
    float w00 = (1.f - wx1) * (1.f - wy1);
    float w10 = wx1 * (1.f - wy1);
    float w01 = (1.f - wx1) * wy1;
    float w11 = wx1 * wy1;
    bool vx0 = (ix0 >= 0) && (ix0 <= WW - 1);
    bool vx1 = (ix0 + 1 >= 0) && (ix0 + 1 <= WW - 1);
    bool vy0 = (iy0 >= 0) && (iy0 <= HH - 1);
    bool vy1 = (iy0 + 1 >= 0) && (iy0 + 1 <= HH - 1);
    int cx0 = min(max(ix0, 0), WW - 1), cx1 = min(max(ix0 + 1, 0), WW - 1);
    int cy0 = min(max(iy0, 0), HH - 1), cy1 = min(max(iy0 + 1, 0), HH - 1);

    float kv[32];
    const float* xb = x + (size_t)(b * CC + g * 32) * NPIX;
#pragma unroll 4
    for (int c = 0; c < 32; c++) {
        const float* xc = xb + c * NPIX;
        float a = 0.f;
        if (vx0 && vy0) a = fmaf(xc[cy0 * WW + cx0], w00, a);
        if (vx1 && vy0) a = fmaf(xc[cy0 * WW + cx1], w10, a);
        if (vx0 && vy1) a = fmaf(xc[cy1 * WW + cx0], w01, a);
        if (vx1 && vy1) a = fmaf(xc[cy1 * WW + cx1], w11, a);
        kv[c] = a;
    }

    const float* wkg = wk + g * 1024;
    const float* wvg = wv + g * 1024;
    for (int o = 0; o < 32; o++) {
        float ak = 0.f, av = 0.f;
#pragma unroll
        for (int c = 0; c < 32; c++) {
            ak = fmaf(kv[c], wkg[o * 32 + c], ak);
            av = fmaf(kv[c], wvg[o * 32 + c], av);
        }
        g_k[(bg * JD + j) * 32 + o] = ak;
        g_v[(bg * JD + j) * 32 + o] = av;
    }
}

// ---------------------------------------------------------------------------
// K3: fused attention, two phases.  grid (8, 72), block 128.
// ---------------------------------------------------------------------------
__global__ void __launch_bounds__(128)
k_attn(const float* __restrict__ cw0, const float* __restrict__ cb0,
       const float* __restrict__ cw1, const float* __restrict__ cb1,
       const float* __restrict__ cw2, const float* __restrict__ cb2) {
    int bg = blockIdx.x;
    int ib = blockIdx.y * TI;
    int t  = threadIdx.x;

    __shared__ float w1s[32 * 32];
    __shared__ float bias_s[TI * BSTR];
    __shared__ float vn0s[JD], vn1s[JD];
    __shared__ float w0s[64], b0s[32], b1s[32], w2s[32];

    for (int idx = t; idx < 1024; idx += 128) w1s[idx] = cw1[idx];
    for (int idx = t; idx < JD; idx += 128) {        // FIX: strided (JD=144 > 128)
        vn0s[idx] = g_vn0[bg * JD + idx];
        vn1s[idx] = g_vn1[bg * JD + idx];
    }
    if (t < 64) w0s[t] = cw0[t];
    if (t < 32) { b0s[t] = cb0[t]; b1s[t] = cb1[t]; w2s[t] = cw2[t]; }
    __syncthreads();

    float b2v = __ldg(cb2);

    // -------- Phase A: CPB bias MLP (36 bias values per thread) --------
#pragma unroll 1
    for (int w = 0; w < (TI * JD) / 128; w++) {
        int p  = w * 128 + t;
        int il = p / JD;
        int j  = p - il * JD;
        int i  = ib + il;
        int ixq = i % WW;
        int iyq = i / WW;
        float qn0 = fmaf((float)ixq, 2.f / 47.f, -1.f);
        float qn1 = fmaf((float)iyq, 2.f / 47.f, -1.f);
        float dx = qn0 - vn0s[j];
        float dy = qn1 - vn1s[j];
        float fx = copysignf(log1pf(fabsf(dx)), dx);
        float fy = copysignf(log1pf(fabsf(dy)), dy);

        float h1[32];
#pragma unroll
        for (int c = 0; c < 32; c++)
            h1[c] = fmaxf(fmaf(fy, w0s[32 + c], fmaf(fx, w0s[c], b0s[c])), 0.f);

        float h2[32];
#pragma unroll
        for (int c = 0; c < 32; c++) h2[c] = b1s[c];
#pragma unroll
        for (int c1 = 0; c1 < 32; c1++) {
            float hv = h1[c1];
            const float4* wr = (const float4*)&w1s[c1 * 32];
#pragma unroll
            for (int q4 = 0; q4 < 8; q4++) {
                float4 w4 = wr[q4];
                h2[q4 * 4 + 0] = fmaf(hv, w4.x, h2[q4 * 4 + 0]);
                h2[q4 * 4 + 1] = fmaf(hv, w4.y, h2[q4 * 4 + 1]);
                h2[q4 * 4 + 2] = fmaf(hv, w4.z, h2[q4 * 4 + 2]);
                h2[q4 * 4 + 3] = fmaf(hv, w4.w, h2[q4 * 4 + 3]);
            }
        }
        float bias = b2v;
#pragma unroll
        for (int c = 0; c < 32; c++) bias = fmaf(fmaxf(h2[c], 0.f), w2s[c], bias);
        bias_s[il * BSTR + j] = bias;
    }
    __syncthreads();

    // -------- Phase B: attention --------
    int il = t >> 2;          // 0..31 query within tile
    int dq = t & 3;           // d-quarter: 8 dims
    int i  = ib + il;

    const float scale = 0.17677669529663687f;  // 32^-0.5
    float qreg[8];
#pragma unroll
    for (int d = 0; d < 8; d++)
        qreg[d] = g_q[(bg * 32 + dq * 8 + d) * NPIX + i] * scale;

    const float4* kb = (const float4*)(g_k + (size_t)bg * JD * 32);
    const float4* vb = (const float4*)(g_v + (size_t)bg * JD * 32);

    float m = -INFINITY, ssum = 0.f;
    float acc[8];
#pragma unroll
    for (int d = 0; d < 8; d++) acc[d] = 0.f;

#pragma unroll 2
    for (int j = 0; j < JD; j++) {
        float4 k0 = __ldg(&kb[j * 8 + dq * 2]);
        float4 k1 = __ldg(&kb[j * 8 + dq * 2 + 1]);
        float sim = qreg[0] * k0.x;
        sim = fmaf(qreg[1], k0.y, sim);
        sim = fmaf(qreg[2], k0.z, sim);
        sim = fmaf(qreg[3], k0.w, sim);
        sim = fmaf(qreg[4], k1.x, sim);
        sim = fmaf(qreg[5], k1.y, sim);
        sim = fmaf(qreg[6], k1.z, sim);
        sim = fmaf(qreg[7], k1.w, sim);
        sim += __shfl_xor_sync(0xffffffffu, sim, 1);
        sim += __shfl_xor_sync(0xffffffffu, sim, 2);

        float logit = sim + bias_s[il * BSTR + j];

        float nm   = fmaxf(m, logit);
        float corr = __expf(m - nm);
        float p    = __expf(logit - nm);
        ssum = fmaf(ssum, corr, p);

        float4 v0 = __ldg(&vb[j * 8 + dq * 2]);
        float4 v1 = __ldg(&vb[j * 8 + dq * 2 + 1]);
        acc[0] = fmaf(p, v0.x, acc[0] * corr);
        acc[1] = fmaf(p, v0.y, acc[1] * corr);
        acc[2] = fmaf(p, v0.z, acc[2] * corr);
        acc[3] = fmaf(p, v0.w, acc[3] * corr);
        acc[4] = fmaf(p, v1.x, acc[4] * corr);
        acc[5] = fmaf(p, v1.y, acc[5] * corr);
        acc[6] = fmaf(p, v1.z, acc[6] * corr);
        acc[7] = fmaf(p, v1.w, acc[7] * corr);
        m = nm;
    }

    float inv = 1.f / ssum;
#pragma unroll
    for (int d = 0; d < 8; d++)
        g_o[(bg * 32 + dq * 8 + d) * NPIX + i] = acc[d] * inv;
}

// ---------------------------------------------------------------------------
// K4: output 1x1 projection + residual; writes both tuple outputs.
//     grid (144, 2), block 256. Tile = 16 pixels; thread = (px, 8 out chans).
// ---------------------------------------------------------------------------
__global__ void __launch_bounds__(256)
k_outproj(const float* __restrict__ x, const float* __restrict__ wo,
          const float* __restrict__ bo, const float* __restrict__ gamma,
          float* __restrict__ out, int out_size) {
    int b    = blockIdx.y;
    int t    = threadIdx.x;
    int px   = t & 15;
    int ochg = t >> 4;          // 0..15 -> out channels [ochg*8, ochg*8+8)
    int ibase = blockIdx.x * 16;

    __shared__ float os_s[16][132];   // [px][c], padded
    for (int idx = t; idx < 2048; idx += 256) {
        int c = idx >> 4, pl = idx & 15;
        os_s[pl][c] = g_o[(size_t)(b * CC + c) * NPIX + ibase + pl];
    }
    __syncthreads();

    float acc[8];
#pragma unroll
    for (int o = 0; o < 8; o++) acc[o] = bo[ochg * 8 + o];

#pragma unroll 4
    for (int c4 = 0; c4 < 32; c4++) {
        float4 os4 = *(const float4*)&os_s[px][c4 * 4];
#pragma unroll
        for (int o = 0; o < 8; o++) {
            float4 w4 = __ldg((const float4*)&wo[(ochg * 8 + o) * CC + c4 * 4]);
            acc[o] = fmaf(os4.x, w4.x, acc[o]);
            acc[o] = fmaf(os4.y, w4.y, acc[o]);
            acc[o] = fmaf(os4.z, w4.z, acc[o]);
            acc[o] = fmaf(os4.w, w4.w, acc[o]);
        }
    }

    float gm = gamma[0];
    const int n1 = BB * CC * NPIX;
    int i = ibase + px;
#pragma unroll
    for (int o = 0; o < 8; o++) {
        int ch  = ochg * 8 + o;
        int idx = (b * CC + ch) * NPIX + i;
        float att = acc[o];
        if (idx < out_size) out[idx] = fmaf(gm, att, x[idx]);
        int idx2 = n1 + idx;
        if (idx2 < out_size) out[idx2] = att;
    }
}

// ---------------------------------------------------------------------------
extern "C" void kernel_launch(void* const* d_in, const int* in_sizes, int n_in,
                              void* d_out, int out_size) {
    const float* x     = (const float*)d_in[0];
    const float* gamma = (const float*)d_in[1];
    const float* wq    = (const float*)d_in[2];
    const float* wk    = (const float*)d_in[3];
    const float* wv    = (const float*)d_in[4];
    const float* wo    = (const float*)d_in[5];
    const float* bo    = (const float*)d_in[6];
    const float* wdw   = (const float*)d_in[7];
    const float* bdw   = (const float*)d_in[8];
    const float* wproj = (const float*)d_in[9];
    const float* cw0   = (const float*)d_in[10];
    const float* cb0   = (const float*)d_in[11];
    const float* cw1   = (const float*)d_in[12];
    const float* cb1   = (const float*)d_in[13];
    const float* cw2   = (const float*)d_in[14];
    const float* cb2   = (const float*)d_in[15];
    float* out = (float*)d_out;

    k_qproj<<<dim3(9, 8), 256>>>(x, wq);
    k_offsets<<<8, 144>>>(x, wdw, bdw, wproj, wk, wv);
    k_attn<<<dim3(8, 72), 128>>>(cw0, cb0, cw1, cb1, cw2, cb2);
    k_outproj<<<dim3(144, 2), 256>>>(x, wo, bo, gamma, out, out_size);
}